// round 1
// baseline (speedup 1.0000x reference)
#include <cuda_runtime.h>
#include <math.h>

// Problem constants
#define BB 8
#define MM 1024
#define DD 768
#define HH 12
#define DHH 64
#define RR 32
#define RF 384
#define RW 384
#define DFF 3072
#define NTOK (BB*MM)   // 8192

// ---------------- scratch (device globals; no allocation allowed) ----------
__device__ float g_W   [DD * 1152];       // repacked [Pq|Pk|Pv] : 768 x 1152
__device__ float g_xP  [NTOK * 1152];     // x @ W
__device__ float g_Q   [BB*HH*MM*DHH];
__device__ float g_K   [BB*HH*MM*DHH];
__device__ float g_V   [BB*HH*MM*DHH];
__device__ float g_attn[NTOK * DD];
__device__ float g_t1  [NTOK * RW];
__device__ float g_t2  [NTOK * DD];
__device__ float g_x1  [NTOK * DD];
__device__ float g_mid [NTOK * RF];
__device__ float g_ff  [NTOK * DFF];
__device__ float g_mid2[NTOK * RF];
__device__ float g_y   [NTOK * DD];

// ---------------- repack (H,D,R) x3 -> (D, 3*H*R) ---------------------------
__global__ void repack_kernel(const float* __restrict__ Pq,
                              const float* __restrict__ Pk,
                              const float* __restrict__ Pv,
                              float* __restrict__ W)
{
    int idx = blockIdx.x * 256 + threadIdx.x;   // < 768*1152
    int d  = idx / 1152;
    int cc = idx - d * 1152;
    int s  = cc / 384;
    int hr = cc - s * 384;
    int h  = hr >> 5, r = hr & 31;
    const float* P = (s == 0) ? Pq : (s == 1) ? Pk : Pv;
    W[idx] = P[((size_t)h * DD + d) * RR + r];
}

// ---------------- generic tiled fp32 GEMM  C[8192 x NN] = A[8192 x K] @ B[K x NN]
// EPI: 0 = none, 1 = +bias, 2 = +bias then exact GELU
template <int EPI>
__global__ __launch_bounds__(256) void gemm_kernel(
    const float* __restrict__ A, const float* __restrict__ Bm,
    const float* __restrict__ bias, float* __restrict__ C,
    int K, int NN)
{
    __shared__ float As[16][132];
    __shared__ float Bs[16][128];
    int tid = threadIdx.x;
    int m0 = blockIdx.y * 128, n0 = blockIdx.x * 128;
    int tx = tid & 15, ty = tid >> 4;
    float acc[8][8];
#pragma unroll
    for (int i = 0; i < 8; i++)
#pragma unroll
        for (int j = 0; j < 8; j++) acc[i][j] = 0.f;

    const float* Ab = A + (size_t)m0 * K;
    const float* Bb = Bm + n0;

    for (int kt = 0; kt < K; kt += 16) {
#pragma unroll
        for (int i = 0; i < 2; i++) {          // A tile: 128x16, store transposed
            int f = tid + i * 256;
            int row = f >> 2, kc = (f & 3) * 4;
            float4 v = *(const float4*)(Ab + (size_t)row * K + kt + kc);
            As[kc + 0][row] = v.x; As[kc + 1][row] = v.y;
            As[kc + 2][row] = v.z; As[kc + 3][row] = v.w;
        }
#pragma unroll
        for (int i = 0; i < 2; i++) {          // B tile: 16x128 direct
            int f = tid + i * 256;
            int row = f >> 5, col = (f & 31) * 4;
            *(float4*)&Bs[row][col] = *(const float4*)(Bb + (size_t)(kt + row) * NN + col);
        }
        __syncthreads();
#pragma unroll
        for (int k = 0; k < 16; k++) {
            float a[8], b[8];
            *(float4*)&a[0] = *(float4*)&As[k][ty * 8];
            *(float4*)&a[4] = *(float4*)&As[k][ty * 8 + 4];
            *(float4*)&b[0] = *(float4*)&Bs[k][tx * 8];
            *(float4*)&b[4] = *(float4*)&Bs[k][tx * 8 + 4];
#pragma unroll
            for (int i = 0; i < 8; i++)
#pragma unroll
                for (int j = 0; j < 8; j++)
                    acc[i][j] += a[i] * b[j];
        }
        __syncthreads();
    }

#pragma unroll
    for (int i = 0; i < 8; i++) {
        int row = m0 + ty * 8 + i;
#pragma unroll
        for (int jj = 0; jj < 8; jj += 4) {
            float4 v;
            float* vp = &v.x;
#pragma unroll
            for (int t = 0; t < 4; t++) {
                float z = acc[i][jj + t];
                if (EPI >= 1) z += bias[n0 + tx * 8 + jj + t];
                if (EPI == 2) z = 0.5f * z * (1.0f + erff(z * 0.70710678118654752f));
                vp[t] = z;
            }
            *(float4*)(C + (size_t)row * NN + n0 + tx * 8 + jj) = v;
        }
    }
}

// ---------------- QKV stage 2: per-head (N x 32) @ (32 x 64) + bias --------
__global__ __launch_bounds__(256) void qkv2_kernel(
    const float* __restrict__ xP,
    const float* __restrict__ Wq, const float* __restrict__ Wk, const float* __restrict__ Wv,
    const float* __restrict__ bq, const float* __restrict__ bk, const float* __restrict__ bv,
    float* __restrict__ Qo, float* __restrict__ Ko, float* __restrict__ Vo)
{
    int s = blockIdx.z, h = blockIdx.y, n0 = blockIdx.x * 64;
    const float* W  = (s == 0) ? Wq : (s == 1) ? Wk : Wv;   // (H,32,64)
    const float* bb = (s == 0) ? bq : (s == 1) ? bk : bv;   // (H,64)
    float* out      = (s == 0) ? Qo : (s == 1) ? Ko : Vo;

    __shared__ float xs[64][36];
    __shared__ float ws[32][64];
    int tid = threadIdx.x;
#pragma unroll
    for (int i = 0; i < 2; i++) {
        int f = tid + i * 256;
        int row = f >> 3, kc = (f & 7) * 4;
        *(float4*)&xs[row][kc] =
            *(const float4*)(xP + (size_t)(n0 + row) * 1152 + s * 384 + h * 32 + kc);
    }
#pragma unroll
    for (int i = 0; i < 2; i++) {
        int f = tid + i * 256;
        int r = f >> 4, c = (f & 15) * 4;
        *(float4*)&ws[r][c] = *(const float4*)(W + ((size_t)h * 32 + r) * 64 + c);
    }
    __syncthreads();

    int c = tid & 63, g = tid >> 6;
    float wcol[32];
#pragma unroll
    for (int k = 0; k < 32; k++) wcol[k] = ws[k][c];
    float bias = bb[h * 64 + c];

#pragma unroll
    for (int i = 0; i < 16; i++) {
        int r = g * 16 + i;
        float acc = 0.f;
#pragma unroll
        for (int k = 0; k < 32; k += 4) {
            float4 x4 = *(float4*)&xs[r][k];
            acc += x4.x * wcol[k] + x4.y * wcol[k + 1] + x4.z * wcol[k + 2] + x4.w * wcol[k + 3];
        }
        int n = n0 + r;
        int b = n >> 10, m = n & 1023;
        out[(((size_t)b * HH + h) * MM + m) * DHH + c] = acc + bias;
    }
}

// ---------------- fused flash attention (fp32, online softmax) --------------
// grid (M/64, B*H), block 256. smem: Qs 64x64, Vs 64x64, Ps 64x64, Kst 64x68.
__global__ __launch_bounds__(256) void flash_kernel(
    const float* __restrict__ Q, const float* __restrict__ K, const float* __restrict__ V,
    const float* __restrict__ mask, float* __restrict__ attn)
{
    extern __shared__ float sm[];
    float* Qs  = sm;                 // [64][64]
    float* Vs  = Qs + 64 * 64;       // [64][64]
    float* Ps  = Vs + 64 * 64;       // [64][64]
    float* Kst = Ps + 64 * 64;       // [64][68]  (k-major, padded)

    int tid = threadIdx.x;
    int m0 = blockIdx.x * 64;
    int bh = blockIdx.y;
    int b  = bh / HH;
    const float* Qb = Q + ((size_t)bh * MM + m0) * DHH;
    const float* Kb = K + (size_t)bh * MM * DHH;
    const float* Vb = V + (size_t)bh * MM * DHH;
    const float* mrow = mask + (size_t)b * MM;

    int tx = tid & 15, ty = tid >> 4;
    int r0 = ty * 4, c0 = tx * 4;

#pragma unroll
    for (int i = 0; i < 4; i++) {
        int f = tid + i * 256;
        int row = f >> 4, col = (f & 15) * 4;
        *(float4*)&Qs[row * 64 + col] = *(const float4*)(Qb + row * 64 + col);
    }

    float mi[4], li[4], o[4][4];
#pragma unroll
    for (int i = 0; i < 4; i++) {
        mi[i] = -1e30f; li[i] = 0.f;
#pragma unroll
        for (int j = 0; j < 4; j++) o[i][j] = 0.f;
    }
    const float scale = 0.125f;

    for (int it = 0; it < 16; it++) {
        int n0 = it * 64;
        __syncthreads();   // protect Kst/Vs/Ps from previous iteration
#pragma unroll
        for (int i = 0; i < 4; i++) {
            int f = tid + i * 256;
            int n = f >> 4, k = (f & 15) * 4;
            float4 kv = *(const float4*)(Kb + (size_t)(n0 + n) * 64 + k);
            Kst[(k + 0) * 68 + n] = kv.x;
            Kst[(k + 1) * 68 + n] = kv.y;
            Kst[(k + 2) * 68 + n] = kv.z;
            Kst[(k + 3) * 68 + n] = kv.w;
            *(float4*)&Vs[n * 64 + k] = *(const float4*)(Vb + (size_t)(n0 + n) * 64 + k);
        }
        __syncthreads();

        float s4[4][4];
#pragma unroll
        for (int i = 0; i < 4; i++)
#pragma unroll
            for (int j = 0; j < 4; j++) s4[i][j] = 0.f;

#pragma unroll
        for (int k = 0; k < 64; k += 4) {
            float q[4][4], kk[4][4];
#pragma unroll
            for (int i = 0; i < 4; i++) *(float4*)q[i]  = *(float4*)&Qs[(r0 + i) * 64 + k];
#pragma unroll
            for (int t = 0; t < 4; t++) *(float4*)kk[t] = *(float4*)&Kst[(k + t) * 68 + c0];
#pragma unroll
            for (int i = 0; i < 4; i++)
#pragma unroll
                for (int t = 0; t < 4; t++)
#pragma unroll
                    for (int j = 0; j < 4; j++)
                        s4[i][j] += q[i][t] * kk[t][j];
        }

        float mk[4];
#pragma unroll
        for (int j = 0; j < 4; j++) mk[j] = mrow[n0 + c0 + j];

#pragma unroll
        for (int i = 0; i < 4; i++) {
#pragma unroll
            for (int j = 0; j < 4; j++) s4[i][j] = s4[i][j] * scale + mk[j];
            float rm = fmaxf(fmaxf(s4[i][0], s4[i][1]), fmaxf(s4[i][2], s4[i][3]));
#pragma unroll
            for (int off = 8; off; off >>= 1)
                rm = fmaxf(rm, __shfl_xor_sync(0xffffffffu, rm, off));
            float mnew = fmaxf(mi[i], rm);
            float al = expf(mi[i] - mnew);
            float ssum = 0.f;
#pragma unroll
            for (int j = 0; j < 4; j++) {
                s4[i][j] = expf(s4[i][j] - mnew);
                ssum += s4[i][j];
            }
#pragma unroll
            for (int off = 8; off; off >>= 1)
                ssum += __shfl_xor_sync(0xffffffffu, ssum, off);
            li[i] = li[i] * al + ssum;
            mi[i] = mnew;
#pragma unroll
            for (int j = 0; j < 4; j++) o[i][j] *= al;
            float4 pv = make_float4(s4[i][0], s4[i][1], s4[i][2], s4[i][3]);
            *(float4*)&Ps[(r0 + i) * 64 + c0] = pv;
        }
        __syncthreads();

#pragma unroll
        for (int nn = 0; nn < 64; nn += 4) {
            float pr[4][4], vv[4][4];
#pragma unroll
            for (int i = 0; i < 4; i++) *(float4*)pr[i] = *(float4*)&Ps[(r0 + i) * 64 + nn];
#pragma unroll
            for (int t = 0; t < 4; t++) *(float4*)vv[t] = *(float4*)&Vs[(nn + t) * 64 + c0];
#pragma unroll
            for (int i = 0; i < 4; i++)
#pragma unroll
                for (int t = 0; t < 4; t++)
#pragma unroll
                    for (int j = 0; j < 4; j++)
                        o[i][j] += pr[i][t] * vv[t][j];
        }
    }

    int h = bh - b * HH;
#pragma unroll
    for (int i = 0; i < 4; i++) {
        float inv = 1.f / li[i];
        float4 v = make_float4(o[i][0] * inv, o[i][1] * inv, o[i][2] * inv, o[i][3] * inv);
        *(float4*)(attn + ((size_t)b * MM + m0 + r0 + i) * DD + h * 64 + c0) = v;
    }
}

// ---------------- LayerNorm over D=768, one block per row -------------------
// in = a[row] + bsrc[row] + (bias? bias : 0), out = g*(in-mu)*rsqrt(var+eps)+beta
__global__ __launch_bounds__(256) void ln_kernel(
    const float* __restrict__ a, const float* __restrict__ bsrc,
    const float* __restrict__ bias,
    const float* __restrict__ g, const float* __restrict__ beta,
    float* __restrict__ out)
{
    int row = blockIdx.x, tid = threadIdx.x;
    __shared__ float red[8];
    size_t base = (size_t)row * DD;
    float v[3];
#pragma unroll
    for (int i = 0; i < 3; i++) {
        int c = tid + i * 256;
        float t = a[base + c] + bsrc[base + c];
        if (bias) t += bias[c];
        v[i] = t;
    }
    float s = v[0] + v[1] + v[2];
#pragma unroll
    for (int off = 16; off; off >>= 1) s += __shfl_xor_sync(0xffffffffu, s, off);
    if ((tid & 31) == 0) red[tid >> 5] = s;
    __syncthreads();
    float mean = (red[0] + red[1] + red[2] + red[3] + red[4] + red[5] + red[6] + red[7]) * (1.f / 768.f);
    __syncthreads();

    float sq = 0.f;
#pragma unroll
    for (int i = 0; i < 3; i++) { float d = v[i] - mean; sq += d * d; }
#pragma unroll
    for (int off = 16; off; off >>= 1) sq += __shfl_xor_sync(0xffffffffu, sq, off);
    if ((tid & 31) == 0) red[tid >> 5] = sq;
    __syncthreads();
    float var = (red[0] + red[1] + red[2] + red[3] + red[4] + red[5] + red[6] + red[7]) * (1.f / 768.f);
    float rstd = rsqrtf(var + 1e-12f);

#pragma unroll
    for (int i = 0; i < 3; i++) {
        int c = tid + i * 256;
        out[base + c] = g[c] * (v[i] - mean) * rstd + beta[c];
    }
}

// ---------------- launch ----------------------------------------------------
extern "C" void kernel_launch(void* const* d_in, const int* in_sizes, int n_in,
                              void* d_out, int out_size)
{
    const float* x    = (const float*)d_in[0];
    const float* mask = (const float*)d_in[1];
    const float* Pq   = (const float*)d_in[2];
    const float* Vq   = (const float*)d_in[3];
    const float* bq   = (const float*)d_in[4];
    const float* Pk   = (const float*)d_in[5];
    const float* Vk   = (const float*)d_in[6];
    const float* bk   = (const float*)d_in[7];
    const float* Pv   = (const float*)d_in[8];
    const float* Vv   = (const float*)d_in[9];
    const float* bv   = (const float*)d_in[10];
    const float* Uo   = (const float*)d_in[11];
    const float* Vo   = (const float*)d_in[12];
    const float* bo   = (const float*)d_in[13];
    const float* U1   = (const float*)d_in[14];
    const float* V1   = (const float*)d_in[15];
    const float* b1   = (const float*)d_in[16];
    const float* U2   = (const float*)d_in[17];
    const float* V2   = (const float*)d_in[18];
    const float* b2   = (const float*)d_in[19];
    const float* ln1g = (const float*)d_in[20];
    const float* ln1b = (const float*)d_in[21];
    const float* ln2g = (const float*)d_in[22];
    const float* ln2b = (const float*)d_in[23];
    float* out = (float*)d_out;

    float *pW, *pxP, *pQ, *pK, *pV, *pattn, *pt1, *pt2, *px1, *pmid, *pff, *pmid2, *py;
    cudaGetSymbolAddress((void**)&pW,    g_W);
    cudaGetSymbolAddress((void**)&pxP,   g_xP);
    cudaGetSymbolAddress((void**)&pQ,    g_Q);
    cudaGetSymbolAddress((void**)&pK,    g_K);
    cudaGetSymbolAddress((void**)&pV,    g_V);
    cudaGetSymbolAddress((void**)&pattn, g_attn);
    cudaGetSymbolAddress((void**)&pt1,   g_t1);
    cudaGetSymbolAddress((void**)&pt2,   g_t2);
    cudaGetSymbolAddress((void**)&px1,   g_x1);
    cudaGetSymbolAddress((void**)&pmid,  g_mid);
    cudaGetSymbolAddress((void**)&pff,   g_ff);
    cudaGetSymbolAddress((void**)&pmid2, g_mid2);
    cudaGetSymbolAddress((void**)&py,    g_y);

    cudaFuncSetAttribute(flash_kernel, cudaFuncAttributeMaxDynamicSharedMemorySize, 66560);

    // 1. repack QKV low-rank down-projections into one 768x1152 matrix
    repack_kernel<<<(DD * 1152) / 256, 256>>>(Pq, Pk, Pv, pW);
    // 2. xP = x @ W   (8192x768 @ 768x1152)
    gemm_kernel<0><<<dim3(1152 / 128, NTOK / 128), 256>>>(x, pW, nullptr, pxP, DD, 1152);
    // 3. Q/K/V = per-head xP_h @ V_{q,k,v}[h] + bias  -> (B,H,M,DH)
    qkv2_kernel<<<dim3(NTOK / 64, HH, 3), 256>>>(pxP, Vq, Vk, Vv, bq, bk, bv, pQ, pK, pV);
    // 4. fused flash attention -> attn in (B,M,D)
    flash_kernel<<<dim3(MM / 64, BB * HH), 256, 66560>>>(pQ, pK, pV, mask, pattn);
    // 5. out-proj low rank: t1 = attn @ Uo ; t2 = t1 @ Vo
    gemm_kernel<0><<<dim3(RW / 128, NTOK / 128), 256>>>(pattn, Uo, nullptr, pt1, DD, RW);
    gemm_kernel<0><<<dim3(DD / 128, NTOK / 128), 256>>>(pt1, Vo, nullptr, pt2, RW, DD);
    // 6. x1 = LN1(x + t2 + bo)
    ln_kernel<<<NTOK, 256>>>(x, pt2, bo, ln1g, ln1b, px1);
    // 7. FFN low rank
    gemm_kernel<0><<<dim3(RF / 128, NTOK / 128), 256>>>(px1, U1, nullptr, pmid, DD, RF);
    gemm_kernel<2><<<dim3(DFF / 128, NTOK / 128), 256>>>(pmid, V1, b1, pff, RF, DFF);
    gemm_kernel<0><<<dim3(RF / 128, NTOK / 128), 256>>>(pff, U2, nullptr, pmid2, DFF, RF);
    gemm_kernel<1><<<dim3(DD / 128, NTOK / 128), 256>>>(pmid2, V2, b2, py, RF, DD);
    // 8. out = LN2(x1 + y)
    ln_kernel<<<NTOK, 256>>>(px1, py, nullptr, ln2g, ln2b, out);
}

// round 2
// speedup vs baseline: 1.0047x; 1.0047x over previous
#include <cuda_runtime.h>
#include <math.h>

// Problem constants
#define BB 8
#define MM 1024
#define DD 768
#define HH 12
#define DHH 64
#define RR 32
#define RF 384
#define RW 384
#define DFF 3072
#define NTOK (BB*MM)   // 8192

// ---------------- scratch (device globals; no allocation allowed) ----------
__device__ float g_W   [DD * 1152];       // repacked [Pq|Pk|Pv] : 768 x 1152
__device__ float g_xP  [NTOK * 1152];     // x @ W
__device__ float g_Q   [BB*HH*MM*DHH];
__device__ float g_K   [BB*HH*MM*DHH];
__device__ float g_V   [BB*HH*MM*DHH];
__device__ float g_attn[NTOK * DD];
__device__ float g_t1  [NTOK * RW];
__device__ float g_t2  [NTOK * DD];
__device__ float g_x1  [NTOK * DD];
__device__ float g_mid [NTOK * RF];
__device__ float g_ff  [NTOK * DFF];
__device__ float g_mid2[NTOK * RF];
__device__ float g_y   [NTOK * DD];

// ---------------- repack (H,D,R) x3 -> (D, 3*H*R) ---------------------------
__global__ void repack_kernel(const float* __restrict__ Pq,
                              const float* __restrict__ Pk,
                              const float* __restrict__ Pv,
                              float* __restrict__ W)
{
    int idx = blockIdx.x * 256 + threadIdx.x;   // < 768*1152
    int d  = idx / 1152;
    int cc = idx - d * 1152;
    int s  = cc / 384;
    int hr = cc - s * 384;
    int h  = hr >> 5, r = hr & 31;
    const float* P = (s == 0) ? Pq : (s == 1) ? Pk : Pv;
    W[idx] = P[((size_t)h * DD + d) * RR + r];
}

// ---------------- generic tiled fp32 GEMM  C[8192 x NN] = A[8192 x K] @ B[K x NN]
// EPI: 0 = none, 1 = +bias, 2 = +bias then exact GELU
template <int EPI>
__global__ __launch_bounds__(256) void gemm_kernel(
    const float* __restrict__ A, const float* __restrict__ Bm,
    const float* __restrict__ bias, float* __restrict__ C,
    int K, int NN)
{
    __shared__ float As[16][132];
    __shared__ float Bs[16][128];
    int tid = threadIdx.x;
    int m0 = blockIdx.y * 128, n0 = blockIdx.x * 128;
    int tx = tid & 15, ty = tid >> 4;
    float acc[8][8];
#pragma unroll
    for (int i = 0; i < 8; i++)
#pragma unroll
        for (int j = 0; j < 8; j++) acc[i][j] = 0.f;

    const float* Ab = A + (size_t)m0 * K;
    const float* Bb = Bm + n0;

    for (int kt = 0; kt < K; kt += 16) {
#pragma unroll
        for (int i = 0; i < 2; i++) {          // A tile: 128x16, store transposed
            int f = tid + i * 256;
            int row = f >> 2, kc = (f & 3) * 4;
            float4 v = *(const float4*)(Ab + (size_t)row * K + kt + kc);
            As[kc + 0][row] = v.x; As[kc + 1][row] = v.y;
            As[kc + 2][row] = v.z; As[kc + 3][row] = v.w;
        }
#pragma unroll
        for (int i = 0; i < 2; i++) {          // B tile: 16x128 direct
            int f = tid + i * 256;
            int row = f >> 5, col = (f & 31) * 4;
            *(float4*)&Bs[row][col] = *(const float4*)(Bb + (size_t)(kt + row) * NN + col);
        }
        __syncthreads();
#pragma unroll
        for (int k = 0; k < 16; k++) {
            float a[8], b[8];
            *(float4*)&a[0] = *(float4*)&As[k][ty * 8];
            *(float4*)&a[4] = *(float4*)&As[k][ty * 8 + 4];
            *(float4*)&b[0] = *(float4*)&Bs[k][tx * 8];
            *(float4*)&b[4] = *(float4*)&Bs[k][tx * 8 + 4];
#pragma unroll
            for (int i = 0; i < 8; i++)
#pragma unroll
                for (int j = 0; j < 8; j++)
                    acc[i][j] += a[i] * b[j];
        }
        __syncthreads();
    }

#pragma unroll
    for (int i = 0; i < 8; i++) {
        int row = m0 + ty * 8 + i;
#pragma unroll
        for (int jj = 0; jj < 8; jj += 4) {
            float4 v;
            float* vp = &v.x;
#pragma unroll
            for (int t = 0; t < 4; t++) {
                float z = acc[i][jj + t];
                if (EPI >= 1) z += bias[n0 + tx * 8 + jj + t];
                if (EPI == 2) z = 0.5f * z * (1.0f + erff(z * 0.70710678118654752f));
                vp[t] = z;
            }
            *(float4*)(C + (size_t)row * NN + n0 + tx * 8 + jj) = v;
        }
    }
}

// ---------------- QKV stage 2: per-head (N x 32) @ (32 x 64) + bias --------
__global__ __launch_bounds__(256) void qkv2_kernel(
    const float* __restrict__ xP,
    const float* __restrict__ Wq, const float* __restrict__ Wk, const float* __restrict__ Wv,
    const float* __restrict__ bq, const float* __restrict__ bk, const float* __restrict__ bv,
    float* __restrict__ Qo, float* __restrict__ Ko, float* __restrict__ Vo)
{
    int s = blockIdx.z, h = blockIdx.y, n0 = blockIdx.x * 64;
    const float* W  = (s == 0) ? Wq : (s == 1) ? Wk : Wv;   // (H,32,64)
    const float* bb = (s == 0) ? bq : (s == 1) ? bk : bv;   // (H,64)
    float* out      = (s == 0) ? Qo : (s == 1) ? Ko : Vo;

    __shared__ float xs[64][36];
    __shared__ float ws[32][64];
    int tid = threadIdx.x;
#pragma unroll
    for (int i = 0; i < 2; i++) {
        int f = tid + i * 256;
        int row = f >> 3, kc = (f & 7) * 4;
        *(float4*)&xs[row][kc] =
            *(const float4*)(xP + (size_t)(n0 + row) * 1152 + s * 384 + h * 32 + kc);
    }
#pragma unroll
    for (int i = 0; i < 2; i++) {
        int f = tid + i * 256;
        int r = f >> 4, c = (f & 15) * 4;
        *(float4*)&ws[r][c] = *(const float4*)(W + ((size_t)h * 32 + r) * 64 + c);
    }
    __syncthreads();

    int c = tid & 63, g = tid >> 6;
    float wcol[32];
#pragma unroll
    for (int k = 0; k < 32; k++) wcol[k] = ws[k][c];
    float bias = bb[h * 64 + c];

#pragma unroll
    for (int i = 0; i < 16; i++) {
        int r = g * 16 + i;
        float acc = 0.f;
#pragma unroll
        for (int k = 0; k < 32; k += 4) {
            float4 x4 = *(float4*)&xs[r][k];
            acc += x4.x * wcol[k] + x4.y * wcol[k + 1] + x4.z * wcol[k + 2] + x4.w * wcol[k + 3];
        }
        int n = n0 + r;
        int b = n >> 10, m = n & 1023;
        out[(((size_t)b * HH + h) * MM + m) * DHH + c] = acc + bias;
    }
}

// ---------------- fused flash attention (fp32, online softmax) --------------
// grid (M/64, B*H), block 256. smem: Qs 64x64, Vs 64x64, Ps 64x64, Kst 64x68.
__global__ __launch_bounds__(256) void flash_kernel(
    const float* __restrict__ Q, const float* __restrict__ K, const float* __restrict__ V,
    const float* __restrict__ mask, float* __restrict__ attn)
{
    extern __shared__ float sm[];
    float* Qs  = sm;                 // [64][64]
    float* Vs  = Qs + 64 * 64;       // [64][64]
    float* Ps  = Vs + 64 * 64;       // [64][64]
    float* Kst = Ps + 64 * 64;       // [64][68]  (k-major, padded)

    int tid = threadIdx.x;
    int m0 = blockIdx.x * 64;
    int bh = blockIdx.y;
    int b  = bh / HH;
    const float* Qb = Q + ((size_t)bh * MM + m0) * DHH;
    const float* Kb = K + (size_t)bh * MM * DHH;
    const float* Vb = V + (size_t)bh * MM * DHH;
    const float* mrow = mask + (size_t)b * MM;

    int tx = tid & 15, ty = tid >> 4;
    int r0 = ty * 4, c0 = tx * 4;

#pragma unroll
    for (int i = 0; i < 4; i++) {
        int f = tid + i * 256;
        int row = f >> 4, col = (f & 15) * 4;
        *(float4*)&Qs[row * 64 + col] = *(const float4*)(Qb + row * 64 + col);
    }

    float mi[4], li[4], o[4][4];
#pragma unroll
    for (int i = 0; i < 4; i++) {
        mi[i] = -1e30f; li[i] = 0.f;
#pragma unroll
        for (int j = 0; j < 4; j++) o[i][j] = 0.f;
    }
    const float scale = 0.125f;

    for (int it = 0; it < 16; it++) {
        int n0 = it * 64;
        __syncthreads();   // protect Kst/Vs/Ps from previous iteration
#pragma unroll
        for (int i = 0; i < 4; i++) {
            int f = tid + i * 256;
            int n = f >> 4, k = (f & 15) * 4;
            float4 kv = *(const float4*)(Kb + (size_t)(n0 + n) * 64 + k);
            Kst[(k + 0) * 68 + n] = kv.x;
            Kst[(k + 1) * 68 + n] = kv.y;
            Kst[(k + 2) * 68 + n] = kv.z;
            Kst[(k + 3) * 68 + n] = kv.w;
            *(float4*)&Vs[n * 64 + k] = *(const float4*)(Vb + (size_t)(n0 + n) * 64 + k);
        }
        __syncthreads();

        float s4[4][4];
#pragma unroll
        for (int i = 0; i < 4; i++)
#pragma unroll
            for (int j = 0; j < 4; j++) s4[i][j] = 0.f;

#pragma unroll
        for (int k = 0; k < 64; k += 4) {
            float q[4][4], kk[4][4];
#pragma unroll
            for (int i = 0; i < 4; i++) *(float4*)q[i]  = *(float4*)&Qs[(r0 + i) * 64 + k];
#pragma unroll
            for (int t = 0; t < 4; t++) *(float4*)kk[t] = *(float4*)&Kst[(k + t) * 68 + c0];
#pragma unroll
            for (int i = 0; i < 4; i++)
#pragma unroll
                for (int t = 0; t < 4; t++)
#pragma unroll
                    for (int j = 0; j < 4; j++)
                        s4[i][j] += q[i][t] * kk[t][j];
        }

        float mk[4];
#pragma unroll
        for (int j = 0; j < 4; j++) mk[j] = mrow[n0 + c0 + j];

#pragma unroll
        for (int i = 0; i < 4; i++) {
#pragma unroll
            for (int j = 0; j < 4; j++) s4[i][j] = s4[i][j] * scale + mk[j];
            float rm = fmaxf(fmaxf(s4[i][0], s4[i][1]), fmaxf(s4[i][2], s4[i][3]));
#pragma unroll
            for (int off = 8; off; off >>= 1)
                rm = fmaxf(rm, __shfl_xor_sync(0xffffffffu, rm, off));
            float mnew = fmaxf(mi[i], rm);
            float al = expf(mi[i] - mnew);
            float ssum = 0.f;
#pragma unroll
            for (int j = 0; j < 4; j++) {
                s4[i][j] = expf(s4[i][j] - mnew);
                ssum += s4[i][j];
            }
#pragma unroll
            for (int off = 8; off; off >>= 1)
                ssum += __shfl_xor_sync(0xffffffffu, ssum, off);
            li[i] = li[i] * al + ssum;
            mi[i] = mnew;
#pragma unroll
            for (int j = 0; j < 4; j++) o[i][j] *= al;
            float4 pv = make_float4(s4[i][0], s4[i][1], s4[i][2], s4[i][3]);
            *(float4*)&Ps[(r0 + i) * 64 + c0] = pv;
        }
        __syncthreads();

#pragma unroll
        for (int nn = 0; nn < 64; nn += 4) {
            float pr[4][4], vv[4][4];
#pragma unroll
            for (int i = 0; i < 4; i++) *(float4*)pr[i] = *(float4*)&Ps[(r0 + i) * 64 + nn];
#pragma unroll
            for (int t = 0; t < 4; t++) *(float4*)vv[t] = *(float4*)&Vs[(nn + t) * 64 + c0];
#pragma unroll
            for (int i = 0; i < 4; i++)
#pragma unroll
                for (int t = 0; t < 4; t++)
#pragma unroll
                    for (int j = 0; j < 4; j++)
                        o[i][j] += pr[i][t] * vv[t][j];
        }
    }

    int h = bh - b * HH;
#pragma unroll
    for (int i = 0; i < 4; i++) {
        float inv = 1.f / li[i];
        float4 v = make_float4(o[i][0] * inv, o[i][1] * inv, o[i][2] * inv, o[i][3] * inv);
        *(float4*)(attn + ((size_t)b * MM + m0 + r0 + i) * DD + h * 64 + c0) = v;
    }
}

// ---------------- LayerNorm over D=768, one block per row -------------------
// in = a[row] + bsrc[row] + (bias? bias : 0), out = g*(in-mu)*rsqrt(var+eps)+beta
__global__ __launch_bounds__(256) void ln_kernel(
    const float* __restrict__ a, const float* __restrict__ bsrc,
    const float* __restrict__ bias,
    const float* __restrict__ g, const float* __restrict__ beta,
    float* __restrict__ out)
{
    int row = blockIdx.x, tid = threadIdx.x;
    __shared__ float red[8];
    size_t base = (size_t)row * DD;
    float v[3];
#pragma unroll
    for (int i = 0; i < 3; i++) {
        int c = tid + i * 256;
        float t = a[base + c] + bsrc[base + c];
        if (bias) t += bias[c];
        v[i] = t;
    }
    float s = v[0] + v[1] + v[2];
#pragma unroll
    for (int off = 16; off; off >>= 1) s += __shfl_xor_sync(0xffffffffu, s, off);
    if ((tid & 31) == 0) red[tid >> 5] = s;
    __syncthreads();
    float mean = (red[0] + red[1] + red[2] + red[3] + red[4] + red[5] + red[6] + red[7]) * (1.f / 768.f);
    __syncthreads();

    float sq = 0.f;
#pragma unroll
    for (int i = 0; i < 3; i++) { float d = v[i] - mean; sq += d * d; }
#pragma unroll
    for (int off = 16; off; off >>= 1) sq += __shfl_xor_sync(0xffffffffu, sq, off);
    if ((tid & 31) == 0) red[tid >> 5] = sq;
    __syncthreads();
    float var = (red[0] + red[1] + red[2] + red[3] + red[4] + red[5] + red[6] + red[7]) * (1.f / 768.f);
    float rstd = rsqrtf(var + 1e-12f);

#pragma unroll
    for (int i = 0; i < 3; i++) {
        int c = tid + i * 256;
        out[base + c] = g[c] * (v[i] - mean) * rstd + beta[c];
    }
}

// ---------------- launch ----------------------------------------------------
extern "C" void kernel_launch(void* const* d_in, const int* in_sizes, int n_in,
                              void* d_out, int out_size)
{
    const float* x    = (const float*)d_in[0];
    const float* mask = (const float*)d_in[1];
    const float* Pq   = (const float*)d_in[2];
    const float* Vq   = (const float*)d_in[3];
    const float* bq   = (const float*)d_in[4];
    const float* Pk   = (const float*)d_in[5];
    const float* Vk   = (const float*)d_in[6];
    const float* bk   = (const float*)d_in[7];
    const float* Pv   = (const float*)d_in[8];
    const float* Vv   = (const float*)d_in[9];
    const float* bv   = (const float*)d_in[10];
    const float* Uo   = (const float*)d_in[11];
    const float* Vo   = (const float*)d_in[12];
    const float* bo   = (const float*)d_in[13];
    const float* U1   = (const float*)d_in[14];
    const float* V1   = (const float*)d_in[15];
    const float* b1   = (const float*)d_in[16];
    const float* U2   = (const float*)d_in[17];
    const float* V2   = (const float*)d_in[18];
    const float* b2   = (const float*)d_in[19];
    const float* ln1g = (const float*)d_in[20];
    const float* ln1b = (const float*)d_in[21];
    const float* ln2g = (const float*)d_in[22];
    const float* ln2b = (const float*)d_in[23];
    float* out = (float*)d_out;

    float *pW, *pxP, *pQ, *pK, *pV, *pattn, *pt1, *pt2, *px1, *pmid, *pff, *pmid2, *py;
    cudaGetSymbolAddress((void**)&pW,    g_W);
    cudaGetSymbolAddress((void**)&pxP,   g_xP);
    cudaGetSymbolAddress((void**)&pQ,    g_Q);
    cudaGetSymbolAddress((void**)&pK,    g_K);
    cudaGetSymbolAddress((void**)&pV,    g_V);
    cudaGetSymbolAddress((void**)&pattn, g_attn);
    cudaGetSymbolAddress((void**)&pt1,   g_t1);
    cudaGetSymbolAddress((void**)&pt2,   g_t2);
    cudaGetSymbolAddress((void**)&px1,   g_x1);
    cudaGetSymbolAddress((void**)&pmid,  g_mid);
    cudaGetSymbolAddress((void**)&pff,   g_ff);
    cudaGetSymbolAddress((void**)&pmid2, g_mid2);
    cudaGetSymbolAddress((void**)&py,    g_y);

    cudaFuncSetAttribute(flash_kernel, cudaFuncAttributeMaxDynamicSharedMemorySize, 66560);

    // 1. repack QKV low-rank down-projections into one 768x1152 matrix
    repack_kernel<<<(DD * 1152) / 256, 256>>>(Pq, Pk, Pv, pW);
    // 2. xP = x @ W   (8192x768 @ 768x1152)
    gemm_kernel<0><<<dim3(1152 / 128, NTOK / 128), 256>>>(x, pW, nullptr, pxP, DD, 1152);
    // 3. Q/K/V = per-head xP_h @ V_{q,k,v}[h] + bias  -> (B,H,M,DH)
    qkv2_kernel<<<dim3(NTOK / 64, HH, 3), 256>>>(pxP, Vq, Vk, Vv, bq, bk, bv, pQ, pK, pV);
    // 4. fused flash attention -> attn in (B,M,D)
    flash_kernel<<<dim3(MM / 64, BB * HH), 256, 66560>>>(pQ, pK, pV, mask, pattn);
    // 5. out-proj low rank: t1 = attn @ Uo ; t2 = t1 @ Vo
    gemm_kernel<0><<<dim3(RW / 128, NTOK / 128), 256>>>(pattn, Uo, nullptr, pt1, DD, RW);
    gemm_kernel<0><<<dim3(DD / 128, NTOK / 128), 256>>>(pt1, Vo, nullptr, pt2, RW, DD);
    // 6. x1 = LN1(x + t2 + bo)
    ln_kernel<<<NTOK, 256>>>(x, pt2, bo, ln1g, ln1b, px1);
    // 7. FFN low rank
    gemm_kernel<0><<<dim3(RF / 128, NTOK / 128), 256>>>(px1, U1, nullptr, pmid, DD, RF);
    gemm_kernel<2><<<dim3(DFF / 128, NTOK / 128), 256>>>(pmid, V1, b1, pff, RF, DFF);
    gemm_kernel<0><<<dim3(RF / 128, NTOK / 128), 256>>>(pff, U2, nullptr, pmid2, DFF, RF);
    gemm_kernel<1><<<dim3(DD / 128, NTOK / 128), 256>>>(pmid2, V2, b2, py, RF, DD);
    // 8. out = LN2(x1 + y)
    ln_kernel<<<NTOK, 256>>>(px1, py, nullptr, ln2g, ln2b, out);
}